// round 6
// baseline (speedup 1.0000x reference)
#include <cuda_runtime.h>

#define NR 1024
#define NC 1024
#define NN (NR*NC)

#define TS   32              // output tile side
#define H    6               // halo (6 one-ring stages)
#define REG  44              // TS + 2*H
#define REG2 (REG*REG)
#define NPR  21              // column-pairs per region row
#define NROWS 42             // region rows [1,43)
#define NPAIR (NPR*NROWS)    // 882
#define NTHR 896

// persistent scratch
__device__ float g_Wp[NN * 8];  // interleaved per-point weights [i*8 + o]
__device__ float g_yA[NN];
__device__ float g_yB[NN];

// Tsit5 coefficients
#define DT (1.0f/32.0f)
#define A21  0.161f
#define A31 -0.008480655492356989f
#define A32  0.335480655492357f
#define A41  2.8971530571054935f
#define A42 -6.359448489975075f
#define A43  4.3622954328695815f
#define A51  5.325864828439257f
#define A52 -11.748883564062828f
#define A53  7.4955393428898365f
#define A54 -0.09249506636175525f
#define A61  5.86145544294642f
#define A62 -12.92096931784711f
#define A63  8.159367898576159f
#define A64 -0.071584973281401f
#define A65 -0.028269050394068383f
#define B1   0.09646076681806523f
#define B2   0.01f
#define B3   0.4798896504144996f
#define B4   1.379008574103742f
#define B5  -3.290069515436081f
#define B6   2.324710524099774f

__device__ __forceinline__ float act(float v) {
    // fmaxf/fminf drop NaN operands -> sanitizes halo garbage too
    return fminf(1.0f, fmaxf(-1.0f, v));
}

__global__ void init_kernel(const float* __restrict__ x) {
    int i = blockIdx.x * blockDim.x + threadIdx.x;
    if (i >= NN) return;
    g_yA[i] = x[i];
#pragma unroll
    for (int o = 0; o < 8; o++) g_Wp[i * 8 + o] = 0.0f;
}

// Scatter edge weights into interleaved per-dst slots keyed by (dst-src) offset.
__global__ void scatter_W(const float* __restrict__ k,
                          const int* __restrict__ src,
                          const int* __restrict__ dst, int ne) {
    int e = blockIdx.x * blockDim.x + threadIdx.x;
    if (e >= ne) return;
    int j = src[e], i = dst[e];
    int dr = (i >> 10) - (j >> 10);      // pos(dst) - pos(src)
    int dc = (i & 1023) - (j & 1023);
    int idx = (dr + 1) * 3 + (dc + 1);   // 0..8, center (4) never occurs
    int o = (idx > 4) ? idx - 1 : idx;   // 0..7
    g_Wp[i * 8 + o] = k[e];
}

// One stage for a horizontally-adjacent point pair (A at p, B at p+1), lc odd.
// smem buffers hold act(u); raw u + act(u) of own points live in registers.
// Weight slot o (offset = dst-src) pairs with source neighbor at p - loff[o].
template<int S>
__device__ __forceinline__ void do_stage(
    const float* __restrict__ uc, float* __restrict__ un,
    bool valid, int p,
    const float wA[8], const float wB[8],
    float kA[5], float kB[5],
    float& uAc, float& uBc, float& aAc, float& aBc,
    float yA, float yB, float zA, float zB,
    bool innA, bool innB, int gA, int gB,
    float* __restrict__ y_out, float* __restrict__ fin)
{
    if (!valid) return;

    // pre-activated neighbor values from smem
    float2 am = *(const float2*)(uc + p - REG - 1);  // row-1, cols lc-1,lc
    float2 bm = *(const float2*)(uc + p - REG + 1);  // row-1, cols lc+1,lc+2
    float2 ap = *(const float2*)(uc + p + REG - 1);  // row+1, cols lc-1,lc
    float2 bp = *(const float2*)(uc + p + REG + 1);  // row+1, cols lc+1,lc+2
    float  lA = uc[p - 1];                           // row  , col lc-1
    float  rB = uc[p + 2];                           // row  , col lc+2

    // Point A (center p): s = z - u + sum_o w[o] * act(u[p - loff[o]])
    float sA = zA - uAc;
    sA = fmaf(wA[0], bp.x, sA);   // src p+REG+1
    sA = fmaf(wA[1], ap.y, sA);   // p+REG
    sA = fmaf(wA[2], ap.x, sA);   // p+REG-1
    sA = fmaf(wA[3], aBc,  sA);   // p+1  (own pair partner, in-register)
    sA = fmaf(wA[4], lA,   sA);   // p-1
    sA = fmaf(wA[5], bm.x, sA);   // p-REG+1
    sA = fmaf(wA[6], am.y, sA);   // p-REG
    sA = fmaf(wA[7], am.x, sA);   // p-REG-1

    // Point B (center p+1)
    float sB = zB - uBc;
    sB = fmaf(wB[0], bp.y, sB);   // p+REG+2
    sB = fmaf(wB[1], bp.x, sB);   // p+REG+1
    sB = fmaf(wB[2], ap.y, sB);   // p+REG
    sB = fmaf(wB[3], rB,   sB);   // p+2
    sB = fmaf(wB[4], aAc,  sB);   // p    (own pair partner, in-register)
    sB = fmaf(wB[5], bm.y, sB);   // p-REG+2
    sB = fmaf(wB[6], bm.x, sB);   // p-REG+1
    sB = fmaf(wB[7], am.y, sB);   // p-REG

    if (S == 6) { // final B-combination -> global y (or clipped output)
        if (innA) {
            float yn = fmaf(DT, B1*kA[0] + B2*kA[1] + B3*kA[2]
                              + B4*kA[3] + B5*kA[4] + B6*sA, yA);
            if (fin) fin[gA] = fminf(1.0f, fmaxf(-1.0f, yn));
            else     y_out[gA] = yn;
        }
        if (innB) {
            float yn = fmaf(DT, B1*kB[0] + B2*kB[1] + B3*kB[2]
                              + B4*kB[3] + B5*kB[4] + B6*sB, yB);
            if (fin) fin[gB] = fminf(1.0f, fmaxf(-1.0f, yn));
            else     y_out[gB] = yn;
        }
        return;
    }

    float nuA, nuB;
    if (S == 1) {
        kA[0] = sA; kB[0] = sB;
        nuA = fmaf(DT, A21 * sA, yA);
        nuB = fmaf(DT, A21 * sB, yB);
    } else if (S == 2) {
        kA[1] = sA; kB[1] = sB;
        nuA = fmaf(DT, A31*kA[0] + A32*sA, yA);
        nuB = fmaf(DT, A31*kB[0] + A32*sB, yB);
    } else if (S == 3) {
        kA[2] = sA; kB[2] = sB;
        nuA = fmaf(DT, A41*kA[0] + A42*kA[1] + A43*sA, yA);
        nuB = fmaf(DT, A41*kB[0] + A42*kB[1] + A43*sB, yB);
    } else if (S == 4) {
        kA[3] = sA; kB[3] = sB;
        nuA = fmaf(DT, A51*kA[0] + A52*kA[1] + A53*kA[2] + A54*sA, yA);
        nuB = fmaf(DT, A51*kB[0] + A52*kB[1] + A53*kB[2] + A54*sB, yB);
    } else { // S == 5
        kA[4] = sA; kB[4] = sB;
        nuA = fmaf(DT, A61*kA[0] + A62*kA[1] + A63*kA[2] + A64*kA[3] + A65*sA, yA);
        nuB = fmaf(DT, A61*kB[0] + A62*kB[1] + A63*kB[2] + A64*kB[3] + A65*sB, yB);
    }
    uAc = nuA;  aAc = act(nuA);
    uBc = nuB;  aBc = act(nuB);
    un[p]     = aAc;
    un[p + 1] = aBc;
}

// One full Tsit5 step for a 32x32 tile with halo-6 redundant compute.
__global__ void __launch_bounds__(NTHR)
step_kernel(int par, const float* __restrict__ z, float* __restrict__ fin) {
    __shared__ __align__(16) float sA_buf[REG2];   // act(u) ping
    __shared__ __align__(16) float sB_buf[REG2];   // act(u) pong

    const float* __restrict__ y_in  = par ? g_yB : g_yA;
    float*       __restrict__ y_out = par ? g_yA : g_yB;

    const int tid = threadIdx.x;
    const int r0 = (int)blockIdx.y * TS - H;
    const int c0 = (int)blockIdx.x * TS - H;

    // fill ping buffer with act(y) (zero-padded OOB); zero pong buffer
    for (int p = tid; p < REG2; p += NTHR) {
        int lr = p / REG, lc = p - lr * REG;
        int r = r0 + lr, c = c0 + lc;
        bool in = ((unsigned)r < NR) & ((unsigned)c < NC);
        sA_buf[p] = in ? act(y_in[r * NC + c]) : 0.0f;
        sB_buf[p] = 0.0f;
    }

    // per-thread pair assignment: row lr in [1,43), cols (lc, lc+1), lc odd
    const bool valid = tid < NPAIR;
    int pr = tid / NPR;
    int pc = tid - pr * NPR;
    int lr = 1 + pr;
    int lc = 1 + 2 * pc;
    int p  = lr * REG + lc;

    int rA = r0 + lr, cA = c0 + lc, cB = cA + 1;
    bool inA = valid & ((unsigned)rA < NR) & ((unsigned)cA < NC);
    bool inB = valid & ((unsigned)rA < NR) & ((unsigned)cB < NC);
    int gA = inA ? (rA * NC + cA) : 0;
    int gB = inB ? (rA * NC + cB) : 0;
    bool innA = valid & (lr >= H) & (lr < H + TS) & (lc   >= H) & (lc   < H + TS);
    bool innB = valid & (lr >= H) & (lr < H + TS) & (lc+1 >= H) & (lc+1 < H + TS);

    float zA = inA ? __ldg(&z[gA]) : 0.0f;
    float zB = inB ? __ldg(&z[gB]) : 0.0f;
    float yA = inA ? __ldg(&y_in[gA]) : 0.0f;
    float yB = inB ? __ldg(&y_in[gB]) : 0.0f;

    float wA[8], wB[8];
    {
        float4 a0 = inA ? *(const float4*)(g_Wp + gA * 8)     : make_float4(0,0,0,0);
        float4 a1 = inA ? *(const float4*)(g_Wp + gA * 8 + 4) : make_float4(0,0,0,0);
        float4 b0 = inB ? *(const float4*)(g_Wp + gB * 8)     : make_float4(0,0,0,0);
        float4 b1 = inB ? *(const float4*)(g_Wp + gB * 8 + 4) : make_float4(0,0,0,0);
        wA[0]=a0.x; wA[1]=a0.y; wA[2]=a0.z; wA[3]=a0.w;
        wA[4]=a1.x; wA[5]=a1.y; wA[6]=a1.z; wA[7]=a1.w;
        wB[0]=b0.x; wB[1]=b0.y; wB[2]=b0.z; wB[3]=b0.w;
        wB[4]=b1.x; wB[5]=b1.y; wB[6]=b1.z; wB[7]=b1.w;
    }

    float uAc = yA, uBc = yB;
    float aAc = act(yA), aBc = act(yB);
    float kA[5], kB[5];

    __syncthreads();

    do_stage<1>(sA_buf, sB_buf, valid, p, wA, wB, kA, kB, uAc, uBc, aAc, aBc,
                yA, yB, zA, zB, innA, innB, gA, gB, y_out, fin);
    __syncthreads();
    do_stage<2>(sB_buf, sA_buf, valid, p, wA, wB, kA, kB, uAc, uBc, aAc, aBc,
                yA, yB, zA, zB, innA, innB, gA, gB, y_out, fin);
    __syncthreads();
    do_stage<3>(sA_buf, sB_buf, valid, p, wA, wB, kA, kB, uAc, uBc, aAc, aBc,
                yA, yB, zA, zB, innA, innB, gA, gB, y_out, fin);
    __syncthreads();
    do_stage<4>(sB_buf, sA_buf, valid, p, wA, wB, kA, kB, uAc, uBc, aAc, aBc,
                yA, yB, zA, zB, innA, innB, gA, gB, y_out, fin);
    __syncthreads();
    do_stage<5>(sA_buf, sB_buf, valid, p, wA, wB, kA, kB, uAc, uBc, aAc, aBc,
                yA, yB, zA, zB, innA, innB, gA, gB, y_out, fin);
    __syncthreads();
    do_stage<6>(sB_buf, sA_buf, valid, p, wA, wB, kA, kB, uAc, uBc, aAc, aBc,
                yA, yB, zA, zB, innA, innB, gA, gB, y_out, fin);
}

extern "C" void kernel_launch(void* const* d_in, const int* in_sizes, int n_in,
                              void* d_out, int out_size) {
    const float* x   = (const float*)d_in[0];
    const float* z   = (const float*)d_in[1];
    const float* k   = (const float*)d_in[2];
    const int*   src = (const int*)d_in[3];
    const int*   dst = (const int*)d_in[4];
    int ne = in_sizes[2];

    init_kernel<<<(NN + 511) / 512, 512>>>(x);
    scatter_W<<<(ne + 511) / 512, 512>>>(k, src, dst, ne);

    dim3 grid(NC / TS, NR / TS);   // 32 x 32 tiles
    for (int s = 0; s < 32; s++) {
        float* fin = (s == 31) ? (float*)d_out : nullptr;  // last step: fused clip -> d_out
        step_kernel<<<grid, NTHR>>>(s & 1, z, fin);
    }
}